// round 15
// baseline (speedup 1.0000x reference)
#include <cuda_runtime.h>
#include <cuda_bf16.h>
#include <cstdint>

#define BB 2
#define HH 16
#define LL 2048
#define DD 64
#define TOPK 64
#define QT 16           // queries per CTA
#define KC 128          // keys per chunk
#define NCHUNK (LL/KC)  // 16
#define NWARP 16
#define NTHREADS 512
#define SS 2056         // score row stride in u16

// ---- smem layout (bytes) ----
#define SC_BYTES   (QT*SS*2)              // 65792 (u16 ordkeys)
#define KBUF_OFF   SC_BYTES
#define KSTAGE     16384                  // K-hi: 128 keys x 128B
#define QHI_OFF    (KBUF_OFF + 2*KSTAGE)  // 98560
#define SMEM_BYTES (QHI_OFF + QT*128)     // 100608 -> 2 CTAs/SM
// per-warp overlays inside the (dead after mainloop) 32KB K buffer:
#define HIST_OFF   KBUF_OFF               // 16 warps * 512B (128 packed u32) = 8KB
#define SIDX_OFF   (KBUF_OFF + 8192)      // 16 warps * 256B = 4KB
#define EIDX_OFF   (KBUF_OFF + 12288)     // 4KB
#define SVAL_OFF   (KBUF_OFF + 16384)     // 4KB
#define KW_OFF     (KBUF_OFF + 20480)     // 16 warps * 64 * float2 = 8KB (ends 28KB)

// ---- persistent bf16-hi split of K (prep kernel output) ----
#define PREP_N (BB*HH*LL*DD/4)
__device__ __align__(16) uint2 KhiG[PREP_N];   // 8MB

__device__ __forceinline__ uint32_t swz(uint32_t o) { return o ^ ((o >> 3) & 0x70u); }
__device__ __forceinline__ uint32_t sptr(const void* p) {
    return (uint32_t)__cvta_generic_to_shared(p);
}
__device__ __forceinline__ void cp_async16(uint32_t dst, const void* src) {
    asm volatile("cp.async.cg.shared.global [%0], [%1], 16;" :: "r"(dst), "l"(src));
}
__device__ __forceinline__ void ldsm_x4(uint32_t a[4], uint32_t addr) {
    asm volatile("ldmatrix.sync.aligned.m8n8.x4.shared.b16 {%0,%1,%2,%3}, [%4];"
                 : "=r"(a[0]), "=r"(a[1]), "=r"(a[2]), "=r"(a[3]) : "r"(addr));
}
__device__ __forceinline__ void mma16816(float c[4], const uint32_t a[4], const uint32_t b[2]) {
    asm volatile("mma.sync.aligned.m16n8k16.row.col.f32.bf16.bf16.f32 "
                 "{%0,%1,%2,%3}, {%4,%5,%6,%7}, {%8,%9}, {%0,%1,%2,%3};"
                 : "+f"(c[0]), "+f"(c[1]), "+f"(c[2]), "+f"(c[3])
                 : "r"(a[0]), "r"(a[1]), "r"(a[2]), "r"(a[3]), "r"(b[0]), "r"(b[1]));
}
// 16-bit monotone ordering key of a float
__device__ __forceinline__ unsigned ord16(float f) {
    unsigned u = __float_as_uint(f);
    u = (u & 0x80000000u) ? ~u : (u | 0x80000000u);
    return u >> 16;
}

// ---- prep: K -> bf16 hi, row-major 128B rows ----
__global__ __launch_bounds__(256) void prep_k_kernel(const float4* __restrict__ K) {
    int i = blockIdx.x * 256 + threadIdx.x;
    float4 v = K[i];
    __nv_bfloat162 h01 = __floats2bfloat162_rn(v.x, v.y);
    __nv_bfloat162 h23 = __floats2bfloat162_rn(v.z, v.w);
    KhiG[i] = make_uint2(*reinterpret_cast<uint32_t*>(&h01),
                         *reinterpret_cast<uint32_t*>(&h23));
}

// packed histogram helpers: word w holds bins w (low u16) and w+128 (high u16)
__device__ __forceinline__ void hadd(uint32_t* hw, unsigned b) {
    atomicAdd(&hw[b & 127u], 1u << ((b & 128u) >> 3));
}
// warp scan over 256 packed bins: find bucket crossing rank r (from top)
__device__ __forceinline__ void hist_scan(const uint32_t* hw, int lane, int r,
                                          int& bsel, int& rnew) {
    const unsigned FULL = 0xFFFFFFFFu;
    const int shift = (lane & 16) ? 16 : 0;   // lanes 16-31 own bins 128-255
    unsigned h[8], s = 0;
    int b0 = lane * 8;
#pragma unroll
    for (int j = 0; j < 8; j++) {
        h[j] = (hw[(lane & 15) * 8 + j] >> shift) & 0xFFFFu;
        s += h[j];
    }
    unsigned t = s;
#pragma unroll
    for (int d = 1; d < 32; d <<= 1) {
        unsigned v = __shfl_down_sync(FULL, t, d);
        if (lane + d < 32) t += v;
    }
    unsigned above = t - s;
    bool cross = (above < (unsigned)r) && ((unsigned)r <= t);
    unsigned cmask = __ballot_sync(FULL, cross);
    int src = __ffs(cmask) - 1;
    int bs = 0, rn = 0;
    if (cross) {
        unsigned cum = above;
#pragma unroll
        for (int j = 7; j >= 0; j--) {
            cum += h[j];
            if (cum >= (unsigned)r) { bs = b0 + j; rn = r - (int)(cum - h[j]); break; }
        }
    }
    bsel = __shfl_sync(FULL, bs, src);
    rnew = __shfl_sync(FULL, rn, src);
}

__global__ __launch_bounds__(NTHREADS, 2)   // <= 64 regs/thread -> 32 warps/SM
void topk_attn_kernel(const float* __restrict__ Qg, const float* __restrict__ Kg,
                      const float* __restrict__ Vg, float* __restrict__ Og)
{
    extern __shared__ char smem[];
    unsigned short* sc16 = (unsigned short*)smem;
    char* qhi = smem + QHI_OFF;
    const uint32_t smem_u32 = sptr(smem);

    const int bh = blockIdx.x >> 7;
    const int qt = blockIdx.x & 127;
    const int q0 = qt * QT;
    const float* Qb = Qg + (size_t)bh * LL * DD;
    const float* Kb = Kg + (size_t)bh * LL * DD;
    const float* Vb = Vg + (size_t)bh * LL * DD;

    const int tid  = threadIdx.x;
    const int lane = tid & 31;
    const int warp = tid >> 5;    // 0..15
    const unsigned FULL = 0xFFFFFFFFu;

    // ---- block-wide K-hi chunk load (16KB) via cp.async ----
    const char* khiG = (const char*)KhiG + ((size_t)bh * LL) * 128;
    auto issue_chunk = [&](int ch) {
        const uint32_t dbase = smem_u32 + KBUF_OFF + (ch & 1) * KSTAGE;
        const size_t gbase = (size_t)ch * KC * 128;
        uint32_t off = (uint32_t)tid * 16;
        cp_async16(dbase + swz(off), khiG + gbase + off);
        off += NTHREADS * 16;
        cp_async16(dbase + swz(off), khiG + gbase + off);
        asm volatile("cp.async.commit_group;" ::: "memory");
    };

    issue_chunk(0);

    // ---- load Q tile (16 x 64 fp32 -> bf16 hi, swizzled) ----
    {
        int qrow = tid >> 5;
        int dc = (tid & 31) * 2;
        float2 qv = *(const float2*)(Qb + (size_t)(q0 + qrow) * DD + dc);
        __nv_bfloat162 hp = __floats2bfloat162_rn(qv.x, qv.y);
        uint32_t off = swz((uint32_t)(qrow * 128 + dc * 2));
        *(uint32_t*)(qhi + off) = *reinterpret_cast<uint32_t*>(&hp);
    }
    __syncthreads();

    // ---- preload A fragments (Q-hi, m16k16 per k-step) ----
    uint32_t Ah[4][4];
    {
        int arow = lane & 15;
        int acb = ((lane >> 4) & 1) * 16;
#pragma unroll
        for (int ks = 0; ks < 4; ks++) {
            uint32_t off = swz((uint32_t)(arow * 128 + ks * 32 + acb));
            ldsm_x4(Ah[ks], sptr(qhi + off));
        }
    }
    // B (K-hi): warp owns keys [warp*8, warp*8+8); x4 covers 2 k-steps
    const uint32_t brow_off = (uint32_t)((warp * 8 + (lane & 7)) * 128 +
                                         ((lane >> 3) & 3) * 16);
    const uint32_t b0off = swz(brow_off);
    const uint32_t b1off = swz(brow_off + 64);

    // ---- main loop: hi-only MMA -> packed u16 ordkey scores ----
    for (int ch = 0; ch < NCHUNK; ch++) {
        asm volatile("cp.async.wait_group 0;" ::: "memory");
        __syncthreads();
        if (ch + 1 < NCHUNK) issue_chunk(ch + 1);

        const uint32_t khi = smem_u32 + KBUF_OFF + (ch & 1) * KSTAGE;
        uint32_t Bh0[4], Bh1[4];
        ldsm_x4(Bh0, khi + b0off);
        ldsm_x4(Bh1, khi + b1off);

        float acc[4] = {0.f, 0.f, 0.f, 0.f};
        mma16816(acc, Ah[0], Bh0);
        mma16816(acc, Ah[1], Bh0 + 2);
        mma16816(acc, Ah[2], Bh1);
        mma16816(acc, Ah[3], Bh1 + 2);

        {
            int qrow = lane >> 2;
            int kcol = ch * KC + warp * 8 + 2 * (lane & 3);
            uint32_t* s32 = (uint32_t*)sc16;
            s32[( qrow      * SS + kcol) >> 1] = ord16(acc[0]) | (ord16(acc[1]) << 16);
            s32[((qrow + 8) * SS + kcol) >> 1] = ord16(acc[2]) | (ord16(acc[3]) << 16);
        }
    }
    __syncthreads();   // scores visible; K buffer dead -> overlays legal

    // ---- per-warp epilogue: 1 query per warp ----
    const int q = warp;
    const uint32_t* row32 = (const uint32_t*)(sc16 + (size_t)q * SS);
    uint32_t* hw    = (uint32_t*)(smem + HIST_OFF) + warp * 128;
    int*      sidx  = (int*)(smem + SIDX_OFF) + warp * 64;
    int*      eidx  = (int*)(smem + EIDX_OFF) + warp * 64;
    float*    svalf = (float*)(smem + SVAL_OFF) + warp * 64;
    float2*   kw    = (float2*)(smem + KW_OFF) + warp * 64;

    // load row once into registers (64 u16 keys / lane)
    uint32_t kp[32];
#pragma unroll
    for (int j = 0; j < 32; j++) kp[j] = row32[j * 32 + lane];

    // pass 1: histogram of top byte (packed bins, from registers)
    for (int w = lane; w < 128; w += 32) hw[w] = 0;
    __syncwarp();
#pragma unroll 4
    for (int j = 0; j < 32; j++) {
        uint32_t w2 = kp[j];
        hadd(hw, (w2 >> 8) & 255u);
        hadd(hw, w2 >> 24);
    }
    __syncwarp();
    int b1d, r1;
    hist_scan(hw, lane, TOPK, b1d, r1);
    __syncwarp();

    // pass 2: histogram of low byte within bucket b1d
    for (int w = lane; w < 128; w += 32) hw[w] = 0;
    __syncwarp();
#pragma unroll 4
    for (int j = 0; j < 32; j++) {
        uint32_t w2 = kp[j];
        if ((int)((w2 >> 8) & 255u) == b1d) hadd(hw, w2 & 255u);
        if ((int)(w2 >> 24) == b1d)         hadd(hw, (w2 >> 16) & 255u);
    }
    __syncwarp();
    int b0sel, r2;
    hist_scan(hw, lane, r1, b0sel, r2);
    const unsigned T16 = ((unsigned)b1d << 8) | (unsigned)b0sel;

    // collect: keys > T16 (index order), then first r2 == T16 in index order
    {
        int cnt = 0, ecnt = 0;
        unsigned lt = (1u << lane) - 1u;
#pragma unroll 4
        for (int j = 0; j < 32; j++) {
            uint32_t w2 = kp[j];
            unsigned klo = w2 & 0xFFFFu, khi2 = w2 >> 16;
            int ilo = j * 64 + 2 * lane;
            bool gt = (klo > T16), eq = (klo == T16);
            unsigned mg = __ballot_sync(FULL, gt);
            unsigned me = __ballot_sync(FULL, eq);
            if (gt) sidx[cnt + __popc(mg & lt)] = ilo;
            if (eq) { int p = ecnt + __popc(me & lt); if (p < TOPK) eidx[p] = ilo; }
            cnt += __popc(mg); ecnt += __popc(me);
            gt = (khi2 > T16); eq = (khi2 == T16);
            mg = __ballot_sync(FULL, gt);
            me = __ballot_sync(FULL, eq);
            if (gt) sidx[cnt + __popc(mg & lt)] = ilo + 1;
            if (eq) { int p = ecnt + __popc(me & lt); if (p < TOPK) eidx[p] = ilo + 1; }
            cnt += __popc(mg); ecnt += __popc(me);
        }
        __syncwarp();
        int r2c = TOPK - cnt;
        for (int j = lane; j < r2c; j += 32) sidx[cnt + j] = eidx[j];
        __syncwarp();
    }

    // ---- exact fp32 rescore: half-warp per key, LDG.128 (2 keys/step) ----
    const int hsel = lane >> 4;          // 0 = lanes 0-15, 1 = lanes 16-31
    const int dbase4 = 4 * (lane & 15);  // 4 dims per lane
    {
        float4 qv4 = *(const float4*)(Qb + (size_t)(q0 + q) * DD + dbase4);
#pragma unroll 1
        for (int p = 0; p < 32; p++) {
            int key = sidx[2 * p + hsel];
            float4 kv = *(const float4*)(Kb + (size_t)key * DD + dbase4);
            float d = qv4.x * kv.x + qv4.y * kv.y + qv4.z * kv.z + qv4.w * kv.w;
#pragma unroll
            for (int o = 8; o; o >>= 1) d += __shfl_xor_sync(FULL, d, o);
            if ((lane & 15) == 0) svalf[2 * p + hsel] = d;
        }
        __syncwarp();
    }

    // ---- softmax (exact fp32) ----
    {
        int k0 = sidx[lane], k1 = sidx[lane + 32];
        float v0 = svalf[lane], v1 = svalf[lane + 32];
        float m = fmaxf(v0, v1);
#pragma unroll
        for (int o = 16; o; o >>= 1) m = fmaxf(m, __shfl_xor_sync(FULL, m, o));
        float e0 = __expf(v0 - m), e1 = __expf(v1 - m);
        float s = e0 + e1;
#pragma unroll
        for (int o = 16; o; o >>= 1) s += __shfl_xor_sync(FULL, s, o);
        float inv = 1.f / s;
        kw[lane]      = make_float2(e0 * inv, __int_as_float(k0));
        kw[lane + 32] = make_float2(e1 * inv, __int_as_float(k1));
    }
    __syncwarp();

    // ---- V gather: half-warp per key, LDG.128 (2 keys/step) ----
    {
        float a0 = 0.f, a1 = 0.f, a2 = 0.f, a3 = 0.f;
#pragma unroll 4
        for (int i = 0; i < 32; i++) {
            float2 t = kw[2 * i + hsel];
            int key = __float_as_int(t.y);
            float4 vv = *(const float4*)(Vb + (size_t)key * DD + dbase4);
            a0 += t.x * vv.x; a1 += t.x * vv.y;
            a2 += t.x * vv.z; a3 += t.x * vv.w;
        }
        // combine the two half-warps (same dims, different key subsets)
        a0 += __shfl_xor_sync(FULL, a0, 16);
        a1 += __shfl_xor_sync(FULL, a1, 16);
        a2 += __shfl_xor_sync(FULL, a2, 16);
        a3 += __shfl_xor_sync(FULL, a3, 16);
        if (lane < 16) {
            size_t ob = ((size_t)bh * LL + q0 + q) * DD;
            *(float4*)(Og + ob + dbase4) = make_float4(a0, a1, a2, a3);
        }
    }
}

extern "C" void kernel_launch(void* const* d_in, const int* in_sizes, int n_in,
                              void* d_out, int out_size)
{
    (void)in_sizes; (void)n_in; (void)out_size;
    const float* Q = (const float*)d_in[0];
    const float* K = (const float*)d_in[1];
    const float* V = (const float*)d_in[2];
    float* O = (float*)d_out;

    prep_k_kernel<<<PREP_N / 256, 256>>>((const float4*)K);

    cudaFuncSetAttribute(topk_attn_kernel,
                         cudaFuncAttributeMaxDynamicSharedMemorySize, SMEM_BYTES);
    dim3 grid(BB * HH * (LL / QT));   // 4096 CTAs
    topk_attn_kernel<<<grid, NTHREADS, SMEM_BYTES>>>(Q, K, V, O);
}

// round 16
// speedup vs baseline: 1.4412x; 1.4412x over previous
#include <cuda_runtime.h>
#include <cuda_bf16.h>
#include <cstdint>

#define BB 2
#define HH 16
#define LL 2048
#define DD 64
#define TOPK 64
#define QT 16           // queries per CTA
#define KC 128          // keys per chunk
#define NCHUNK (LL/KC)  // 16
#define NWARP 16
#define NTHREADS 512
#define SS 2056         // score row stride in u16

// ---- smem layout (bytes) ----
#define SC_BYTES   (QT*SS*2)              // 65792 (u16 ordkeys), 128B-aligned
#define KBUF_OFF   SC_BYTES
#define KSTAGE     16384                  // K-hi: 128 keys x 128B
#define QHI_OFF    (KBUF_OFF + 2*KSTAGE)  // 98560
#define SMEM_BYTES (QHI_OFF + QT*128)     // 100608 -> 2 CTAs/SM
// per-warp overlays inside the (dead after mainloop) K buffer (28KB < 32KB):
#define HIST_OFF   KBUF_OFF               // 16 warps * 1KB
#define SIDX_OFF   (KBUF_OFF + 16384)     // 16 warps * 256B
#define EIDX_OFF   (KBUF_OFF + 20480)
#define SVAL_OFF   (KBUF_OFF + 24576)

// ---- persistent bf16-hi split of K (prep kernel output) ----
#define PREP_N (BB*HH*LL*DD/4)
__device__ __align__(16) uint2 KhiG[PREP_N];   // 8MB

__device__ __forceinline__ uint32_t swz(uint32_t o) { return o ^ ((o >> 3) & 0x70u); }
__device__ __forceinline__ uint32_t sptr(const void* p) {
    return (uint32_t)__cvta_generic_to_shared(p);
}
__device__ __forceinline__ void cp_async16(uint32_t dst, const void* src) {
    asm volatile("cp.async.cg.shared.global [%0], [%1], 16;" :: "r"(dst), "l"(src));
}
__device__ __forceinline__ void ldsm_x4(uint32_t a[4], uint32_t addr) {
    asm volatile("ldmatrix.sync.aligned.m8n8.x4.shared.b16 {%0,%1,%2,%3}, [%4];"
                 : "=r"(a[0]), "=r"(a[1]), "=r"(a[2]), "=r"(a[3]) : "r"(addr));
}
__device__ __forceinline__ void mma16816(float c[4], const uint32_t a[4], const uint32_t b[2]) {
    asm volatile("mma.sync.aligned.m16n8k16.row.col.f32.bf16.bf16.f32 "
                 "{%0,%1,%2,%3}, {%4,%5,%6,%7}, {%8,%9}, {%0,%1,%2,%3};"
                 : "+f"(c[0]), "+f"(c[1]), "+f"(c[2]), "+f"(c[3])
                 : "r"(a[0]), "r"(a[1]), "r"(a[2]), "r"(a[3]), "r"(b[0]), "r"(b[1]));
}
// 16-bit monotone ordering key of a float
__device__ __forceinline__ unsigned ord16(float f) {
    unsigned u = __float_as_uint(f);
    u = (u & 0x80000000u) ? ~u : (u | 0x80000000u);
    return u >> 16;
}

// ---- prep: K -> bf16 hi, row-major 128B rows ----
__global__ __launch_bounds__(256) void prep_k_kernel(const float4* __restrict__ K) {
    int i = blockIdx.x * 256 + threadIdx.x;
    float4 v = K[i];
    __nv_bfloat162 h01 = __floats2bfloat162_rn(v.x, v.y);
    __nv_bfloat162 h23 = __floats2bfloat162_rn(v.z, v.w);
    KhiG[i] = make_uint2(*reinterpret_cast<uint32_t*>(&h01),
                         *reinterpret_cast<uint32_t*>(&h23));
}

// warp-level scan over a 256-bin histogram: find digit bucket crossing rank r
__device__ __forceinline__ void hist_scan(const uint32_t* myhist, int lane, int r,
                                          int& bsel, int& rnew) {
    const unsigned FULL = 0xFFFFFFFFu;
    unsigned h[8], s = 0;
    int b0 = lane * 8;
#pragma unroll
    for (int j = 0; j < 8; j++) { h[j] = myhist[b0 + j]; s += h[j]; }
    unsigned t = s;
#pragma unroll
    for (int d = 1; d < 32; d <<= 1) {
        unsigned v = __shfl_down_sync(FULL, t, d);
        if (lane + d < 32) t += v;
    }
    unsigned above = t - s;
    bool cross = (above < (unsigned)r) && ((unsigned)r <= t);
    unsigned cmask = __ballot_sync(FULL, cross);
    int src = __ffs(cmask) - 1;
    int bs = 0, rn = 0;
    if (cross) {
        unsigned cum = above;
#pragma unroll
        for (int j = 7; j >= 0; j--) {
            cum += h[j];
            if (cum >= (unsigned)r) { bs = b0 + j; rn = r - (int)(cum - h[j]); break; }
        }
    }
    bsel = __shfl_sync(FULL, bs, src);
    rnew = __shfl_sync(FULL, rn, src);
}

__global__ __launch_bounds__(NTHREADS, 2)   // <= 64 regs/thread -> 32 warps/SM
void topk_attn_kernel(const float* __restrict__ Qg, const float* __restrict__ Kg,
                      const float* __restrict__ Vg, float* __restrict__ Og)
{
    extern __shared__ char smem[];
    unsigned short* sc16 = (unsigned short*)smem;
    char* qhi = smem + QHI_OFF;
    const uint32_t smem_u32 = sptr(smem);

    const int bh = blockIdx.x >> 7;
    const int qt = blockIdx.x & 127;
    const int q0 = qt * QT;
    const float* Qb = Qg + (size_t)bh * LL * DD;
    const float* Kb = Kg + (size_t)bh * LL * DD;
    const float* Vb = Vg + (size_t)bh * LL * DD;

    const int tid  = threadIdx.x;
    const int lane = tid & 31;
    const int warp = tid >> 5;    // 0..15
    const unsigned FULL = 0xFFFFFFFFu;

    // ---- block-wide K-hi chunk load (16KB) via cp.async ----
    const char* khiG = (const char*)KhiG + ((size_t)bh * LL) * 128;
    auto issue_chunk = [&](int ch) {
        const uint32_t dbase = smem_u32 + KBUF_OFF + (ch & 1) * KSTAGE;
        const size_t gbase = (size_t)ch * KC * 128;
        uint32_t off = (uint32_t)tid * 16;            // 512 thr x 16B = 8KB
        cp_async16(dbase + swz(off), khiG + gbase + off);
        off += NTHREADS * 16;
        cp_async16(dbase + swz(off), khiG + gbase + off);
        asm volatile("cp.async.commit_group;" ::: "memory");
    };

    issue_chunk(0);

    // ---- load Q tile (16 x 64 fp32 -> bf16 hi, swizzled) ----
    {
        int qrow = tid >> 5;          // 0..15
        int dc = (tid & 31) * 2;      // 0..62
        float2 qv = *(const float2*)(Qb + (size_t)(q0 + qrow) * DD + dc);
        __nv_bfloat162 hp = __floats2bfloat162_rn(qv.x, qv.y);
        uint32_t off = swz((uint32_t)(qrow * 128 + dc * 2));
        *(uint32_t*)(qhi + off) = *reinterpret_cast<uint32_t*>(&hp);
    }
    __syncthreads();

    // ---- preload A fragments (Q-hi, m16k16 per k-step): 16 regs ----
    uint32_t Ah[4][4];
    {
        int arow = lane & 15;
        int acb = ((lane >> 4) & 1) * 16;
#pragma unroll
        for (int ks = 0; ks < 4; ks++) {
            uint32_t off = swz((uint32_t)(arow * 128 + ks * 32 + acb));
            ldsm_x4(Ah[ks], sptr(qhi + off));
        }
    }
    // B (K-hi): warp owns keys [warp*8, warp*8+8); x4 covers 2 k-steps
    const uint32_t brow_off = (uint32_t)((warp * 8 + (lane & 7)) * 128 +
                                         ((lane >> 3) & 3) * 16);
    const uint32_t b0off = swz(brow_off);
    const uint32_t b1off = swz(brow_off + 64);

    // ---- main loop: hi-only MMA -> packed u16 ordkey scores ----
    for (int ch = 0; ch < NCHUNK; ch++) {
        asm volatile("cp.async.wait_group 0;" ::: "memory");
        __syncthreads();
        if (ch + 1 < NCHUNK) issue_chunk(ch + 1);

        const uint32_t khi = smem_u32 + KBUF_OFF + (ch & 1) * KSTAGE;
        uint32_t Bh0[4], Bh1[4];
        ldsm_x4(Bh0, khi + b0off);
        ldsm_x4(Bh1, khi + b1off);

        float acc[4] = {0.f, 0.f, 0.f, 0.f};
        mma16816(acc, Ah[0], Bh0);
        mma16816(acc, Ah[1], Bh0 + 2);
        mma16816(acc, Ah[2], Bh1);
        mma16816(acc, Ah[3], Bh1 + 2);

        // rows = queries, cols = keys; pack adjacent key pair -> one STS.32
        {
            int qrow = lane >> 2;
            int kcol = ch * KC + warp * 8 + 2 * (lane & 3);
            uint32_t* s32 = (uint32_t*)sc16;
            s32[( qrow      * SS + kcol) >> 1] = ord16(acc[0]) | (ord16(acc[1]) << 16);
            s32[((qrow + 8) * SS + kcol) >> 1] = ord16(acc[2]) | (ord16(acc[3]) << 16);
        }
    }
    __syncthreads();   // scores visible; K buffer dead -> overlays legal

    // ---- per-warp epilogue: 1 query per warp, selection reads smem ----
    const int q = warp;
    const uint32_t* row32 = (const uint32_t*)(sc16 + (size_t)q * SS);
    uint32_t* myhist = (uint32_t*)(smem + HIST_OFF) + warp * 256;
    int*      sidx   = (int*)(smem + SIDX_OFF) + warp * 64;
    int*      eidx   = (int*)(smem + EIDX_OFF) + warp * 64;
    float*    svalf  = (float*)(smem + SVAL_OFF) + warp * 64;

    // pass 1: histogram of top byte
    for (int b = lane; b < 256; b += 32) myhist[b] = 0;
    __syncwarp();
#pragma unroll 4
    for (int j = 0; j < 32; j++) {
        uint32_t w2 = row32[j * 32 + lane];
        atomicAdd(&myhist[(w2 >> 8) & 255u], 1u);
        atomicAdd(&myhist[w2 >> 24], 1u);
    }
    __syncwarp();
    int b1d, r1;
    hist_scan(myhist, lane, TOPK, b1d, r1);
    __syncwarp();

    // pass 2: histogram of low byte within bucket b1d
    for (int b = lane; b < 256; b += 32) myhist[b] = 0;
    __syncwarp();
#pragma unroll 4
    for (int j = 0; j < 32; j++) {
        uint32_t w2 = row32[j * 32 + lane];
        if ((int)((w2 >> 8) & 255u) == b1d) atomicAdd(&myhist[w2 & 255u], 1u);
        if ((int)(w2 >> 24) == b1d)         atomicAdd(&myhist[(w2 >> 16) & 255u], 1u);
    }
    __syncwarp();
    int b0sel, r2;
    hist_scan(myhist, lane, r1, b0sel, r2);
    const unsigned T16 = ((unsigned)b1d << 8) | (unsigned)b0sel;

    // pass 3: collect keys > T16, then first r2 == T16 in index order
    {
        int cnt = 0, ecnt = 0;
        unsigned lt = (1u << lane) - 1u;
#pragma unroll 4
        for (int j = 0; j < 32; j++) {
            uint32_t w2 = row32[j * 32 + lane];
            unsigned klo = w2 & 0xFFFFu, khi2 = w2 >> 16;
            int ilo = j * 64 + 2 * lane;
            bool gt = (klo > T16), eq = (klo == T16);
            unsigned mg = __ballot_sync(FULL, gt);
            unsigned me = __ballot_sync(FULL, eq);
            if (gt) sidx[cnt + __popc(mg & lt)] = ilo;
            if (eq) { int p = ecnt + __popc(me & lt); if (p < TOPK) eidx[p] = ilo; }
            cnt += __popc(mg); ecnt += __popc(me);
            gt = (khi2 > T16); eq = (khi2 == T16);
            mg = __ballot_sync(FULL, gt);
            me = __ballot_sync(FULL, eq);
            if (gt) sidx[cnt + __popc(mg & lt)] = ilo + 1;
            if (eq) { int p = ecnt + __popc(me & lt); if (p < TOPK) eidx[p] = ilo + 1; }
            cnt += __popc(mg); ecnt += __popc(me);
        }
        __syncwarp();
        for (int j = lane; j < r2; j += 32) sidx[cnt + j] = eidx[j];
        __syncwarp();
    }

    // ---- exact fp32 rescore: half-warp per key, LDG.128 (2 keys/step) ----
    const int hsel = lane >> 4;          // 0 = lanes 0-15, 1 = lanes 16-31
    const int dbase4 = 4 * (lane & 15);  // 4 dims per lane
    {
        float4 qv4 = *(const float4*)(Qb + (size_t)(q0 + q) * DD + dbase4);
#pragma unroll 1
        for (int p = 0; p < 32; p++) {
            int key = sidx[2 * p + hsel];
            float4 kv = *(const float4*)(Kb + (size_t)key * DD + dbase4);
            float d = qv4.x * kv.x + qv4.y * kv.y + qv4.z * kv.z + qv4.w * kv.w;
#pragma unroll
            for (int o = 8; o; o >>= 1) d += __shfl_xor_sync(FULL, d, o);
            if ((lane & 15) == 0) svalf[2 * p + hsel] = d;
        }
        __syncwarp();
    }

    // ---- softmax (exact fp32) + V gather (half-warp per key, LDG.128) ----
    {
        int k0 = sidx[lane], k1 = sidx[lane + 32];
        float v0 = svalf[lane], v1 = svalf[lane + 32];
        float m = fmaxf(v0, v1);
#pragma unroll
        for (int o = 16; o; o >>= 1) m = fmaxf(m, __shfl_xor_sync(FULL, m, o));
        float e0 = __expf(v0 - m), e1 = __expf(v1 - m);
        float s = e0 + e1;
#pragma unroll
        for (int o = 16; o; o >>= 1) s += __shfl_xor_sync(FULL, s, o);
        float inv = 1.f / s;
        float w0 = e0 * inv, w1 = e1 * inv;

        float a0 = 0.f, a1 = 0.f, a2 = 0.f, a3 = 0.f;
        // slots 0..31 (weights w0/keys k0): half-warp h handles slot 2i+h
#pragma unroll 4
        for (int i = 0; i < 16; i++) {
            int src = 2 * i + hsel;
            float w = __shfl_sync(FULL, w0, src);
            int key = __shfl_sync(FULL, k0, src);
            float4 vv = *(const float4*)(Vb + (size_t)key * DD + dbase4);
            a0 += w * vv.x; a1 += w * vv.y; a2 += w * vv.z; a3 += w * vv.w;
        }
        // slots 32..63 (weights w1/keys k1)
#pragma unroll 4
        for (int i = 0; i < 16; i++) {
            int src = 2 * i + hsel;
            float w = __shfl_sync(FULL, w1, src);
            int key = __shfl_sync(FULL, k1, src);
            float4 vv = *(const float4*)(Vb + (size_t)key * DD + dbase4);
            a0 += w * vv.x; a1 += w * vv.y; a2 += w * vv.z; a3 += w * vv.w;
        }
        // combine the two half-warps (same dims, disjoint key subsets)
        a0 += __shfl_xor_sync(FULL, a0, 16);
        a1 += __shfl_xor_sync(FULL, a1, 16);
        a2 += __shfl_xor_sync(FULL, a2, 16);
        a3 += __shfl_xor_sync(FULL, a3, 16);
        if (lane < 16) {
            size_t ob = ((size_t)bh * LL + q0 + q) * DD;
            *(float4*)(Og + ob + dbase4) = make_float4(a0, a1, a2, a3);
        }
    }
}

extern "C" void kernel_launch(void* const* d_in, const int* in_sizes, int n_in,
                              void* d_out, int out_size)
{
    (void)in_sizes; (void)n_in; (void)out_size;
    const float* Q = (const float*)d_in[0];
    const float* K = (const float*)d_in[1];
    const float* V = (const float*)d_in[2];
    float* O = (float*)d_out;

    prep_k_kernel<<<PREP_N / 256, 256>>>((const float4*)K);

    cudaFuncSetAttribute(topk_attn_kernel,
                         cudaFuncAttributeMaxDynamicSharedMemorySize, SMEM_BYTES);
    dim3 grid(BB * HH * (LL / QT));   // 4096 CTAs
    topk_attn_kernel<<<grid, NTHREADS, SMEM_BYTES>>>(Q, K, V, O);
}

// round 17
// speedup vs baseline: 1.5516x; 1.0766x over previous
#include <cuda_runtime.h>
#include <cuda_bf16.h>
#include <cstdint>

#define BB 2
#define HH 16
#define LL 2048
#define DD 64
#define TOPK 64
#define QT 16           // queries per CTA
#define KC 128          // keys per chunk
#define NCHUNK (LL/KC)  // 16
#define NWARP 16
#define NTHREADS 512
#define SS 2056         // score row stride in u16

// ---- smem layout (bytes) ----
#define SC_BYTES   (QT*SS*2)              // 65792 (u16 ordkeys), 128B-aligned
#define KBUF_OFF   SC_BYTES
#define KSTAGE     16384                  // K-hi: 128 keys x 128B
#define QHI_OFF    (KBUF_OFF + 2*KSTAGE)  // 98560
#define SMEM_BYTES (QHI_OFF + QT*128)     // 100608 -> 2 CTAs/SM
// per-warp overlays inside the (dead after mainloop) K buffer (28KB < 32KB):
#define HIST_OFF   KBUF_OFF               // 16 warps * 1KB
#define SIDX_OFF   (KBUF_OFF + 16384)     // 16 warps * 256B
#define EIDX_OFF   (KBUF_OFF + 20480)
#define SVAL_OFF   (KBUF_OFF + 24576)

// ---- persistent bf16-hi split of K (prep kernel output) ----
#define PREP_N (BB*HH*LL*DD/4)
__device__ __align__(16) uint2 KhiG[PREP_N];   // 8MB

__device__ __forceinline__ uint32_t swz(uint32_t o) { return o ^ ((o >> 3) & 0x70u); }
__device__ __forceinline__ uint32_t sptr(const void* p) {
    return (uint32_t)__cvta_generic_to_shared(p);
}
__device__ __forceinline__ void cp_async16(uint32_t dst, const void* src) {
    asm volatile("cp.async.cg.shared.global [%0], [%1], 16;" :: "r"(dst), "l"(src));
}
__device__ __forceinline__ void ldsm_x4(uint32_t a[4], uint32_t addr) {
    asm volatile("ldmatrix.sync.aligned.m8n8.x4.shared.b16 {%0,%1,%2,%3}, [%4];"
                 : "=r"(a[0]), "=r"(a[1]), "=r"(a[2]), "=r"(a[3]) : "r"(addr));
}
__device__ __forceinline__ void mma16816(float c[4], const uint32_t a[4], const uint32_t b[2]) {
    asm volatile("mma.sync.aligned.m16n8k16.row.col.f32.bf16.bf16.f32 "
                 "{%0,%1,%2,%3}, {%4,%5,%6,%7}, {%8,%9}, {%0,%1,%2,%3};"
                 : "+f"(c[0]), "+f"(c[1]), "+f"(c[2]), "+f"(c[3])
                 : "r"(a[0]), "r"(a[1]), "r"(a[2]), "r"(a[3]), "r"(b[0]), "r"(b[1]));
}
// 16-bit monotone ordering key of a float
__device__ __forceinline__ unsigned ord16(float f) {
    unsigned u = __float_as_uint(f);
    u = (u & 0x80000000u) ? ~u : (u | 0x80000000u);
    return u >> 16;
}

// ---- prep: K -> bf16 hi, row-major 128B rows ----
__global__ __launch_bounds__(256) void prep_k_kernel(const float4* __restrict__ K) {
    int i = blockIdx.x * 256 + threadIdx.x;
    float4 v = K[i];
    __nv_bfloat162 h01 = __floats2bfloat162_rn(v.x, v.y);
    __nv_bfloat162 h23 = __floats2bfloat162_rn(v.z, v.w);
    KhiG[i] = make_uint2(*reinterpret_cast<uint32_t*>(&h01),
                         *reinterpret_cast<uint32_t*>(&h23));
}

// warp-level scan over a 256-bin histogram: find digit bucket crossing rank r
__device__ __forceinline__ void hist_scan(const uint32_t* myhist, int lane, int r,
                                          int& bsel, int& rnew) {
    const unsigned FULL = 0xFFFFFFFFu;
    unsigned h[8], s = 0;
    int b0 = lane * 8;
#pragma unroll
    for (int j = 0; j < 8; j++) { h[j] = myhist[b0 + j]; s += h[j]; }
    unsigned t = s;
#pragma unroll
    for (int d = 1; d < 32; d <<= 1) {
        unsigned v = __shfl_down_sync(FULL, t, d);
        if (lane + d < 32) t += v;
    }
    unsigned above = t - s;
    bool cross = (above < (unsigned)r) && ((unsigned)r <= t);
    unsigned cmask = __ballot_sync(FULL, cross);
    int src = __ffs(cmask) - 1;
    int bs = 0, rn = 0;
    if (cross) {
        unsigned cum = above;
#pragma unroll
        for (int j = 7; j >= 0; j--) {
            cum += h[j];
            if (cum >= (unsigned)r) { bs = b0 + j; rn = r - (int)(cum - h[j]); break; }
        }
    }
    bsel = __shfl_sync(FULL, bs, src);
    rnew = __shfl_sync(FULL, rn, src);
}

__global__ __launch_bounds__(NTHREADS, 2)   // <= 64 regs/thread -> 32 warps/SM
void topk_attn_kernel(const float* __restrict__ Qg, const float* __restrict__ Kg,
                      const float* __restrict__ Vg, float* __restrict__ Og)
{
    extern __shared__ char smem[];
    unsigned short* sc16 = (unsigned short*)smem;
    char* qhi = smem + QHI_OFF;
    const uint32_t smem_u32 = sptr(smem);

    const int bh = blockIdx.x >> 7;
    const int qt = blockIdx.x & 127;
    const int q0 = qt * QT;
    const float* Qb = Qg + (size_t)bh * LL * DD;
    const float* Kb = Kg + (size_t)bh * LL * DD;
    const float* Vb = Vg + (size_t)bh * LL * DD;

    const int tid  = threadIdx.x;
    const int lane = tid & 31;
    const int warp = tid >> 5;    // 0..15
    const unsigned FULL = 0xFFFFFFFFu;

    // ---- block-wide K-hi chunk load (16KB) via cp.async ----
    const char* khiG = (const char*)KhiG + ((size_t)bh * LL) * 128;
    auto issue_chunk = [&](int ch) {
        const uint32_t dbase = smem_u32 + KBUF_OFF + (ch & 1) * KSTAGE;
        const size_t gbase = (size_t)ch * KC * 128;
        uint32_t off = (uint32_t)tid * 16;            // 512 thr x 16B = 8KB
        cp_async16(dbase + swz(off), khiG + gbase + off);
        off += NTHREADS * 16;
        cp_async16(dbase + swz(off), khiG + gbase + off);
        asm volatile("cp.async.commit_group;" ::: "memory");
    };

    issue_chunk(0);

    // ---- load Q tile (16 x 64 fp32 -> bf16 hi, swizzled) ----
    {
        int qrow = tid >> 5;          // 0..15
        int dc = (tid & 31) * 2;      // 0..62
        float2 qv = *(const float2*)(Qb + (size_t)(q0 + qrow) * DD + dc);
        __nv_bfloat162 hp = __floats2bfloat162_rn(qv.x, qv.y);
        uint32_t off = swz((uint32_t)(qrow * 128 + dc * 2));
        *(uint32_t*)(qhi + off) = *reinterpret_cast<uint32_t*>(&hp);
    }
    __syncthreads();

    // ---- preload A fragments (Q-hi, m16k16 per k-step): 16 regs ----
    uint32_t Ah[4][4];
    {
        int arow = lane & 15;
        int acb = ((lane >> 4) & 1) * 16;
#pragma unroll
        for (int ks = 0; ks < 4; ks++) {
            uint32_t off = swz((uint32_t)(arow * 128 + ks * 32 + acb));
            ldsm_x4(Ah[ks], sptr(qhi + off));
        }
    }
    // B (K-hi): warp owns keys [warp*8, warp*8+8); x4 covers 2 k-steps
    const uint32_t brow_off = (uint32_t)((warp * 8 + (lane & 7)) * 128 +
                                         ((lane >> 3) & 3) * 16);
    const uint32_t b0off = swz(brow_off);
    const uint32_t b1off = swz(brow_off + 64);

    // ---- main loop: hi-only MMA -> packed u16 ordkey scores ----
    for (int ch = 0; ch < NCHUNK; ch++) {
        asm volatile("cp.async.wait_group 0;" ::: "memory");
        __syncthreads();
        if (ch + 1 < NCHUNK) issue_chunk(ch + 1);

        const uint32_t khi = smem_u32 + KBUF_OFF + (ch & 1) * KSTAGE;
        uint32_t Bh0[4], Bh1[4];
        ldsm_x4(Bh0, khi + b0off);
        ldsm_x4(Bh1, khi + b1off);

        float acc[4] = {0.f, 0.f, 0.f, 0.f};
        mma16816(acc, Ah[0], Bh0);
        mma16816(acc, Ah[1], Bh0 + 2);
        mma16816(acc, Ah[2], Bh1);
        mma16816(acc, Ah[3], Bh1 + 2);

        // rows = queries, cols = keys; pack adjacent key pair -> one STS.32
        {
            int qrow = lane >> 2;
            int kcol = ch * KC + warp * 8 + 2 * (lane & 3);
            uint32_t* s32 = (uint32_t*)sc16;
            s32[( qrow      * SS + kcol) >> 1] = ord16(acc[0]) | (ord16(acc[1]) << 16);
            s32[((qrow + 8) * SS + kcol) >> 1] = ord16(acc[2]) | (ord16(acc[3]) << 16);
        }
    }
    __syncthreads();   // scores visible; K buffer dead -> overlays legal

    // ---- per-warp epilogue: 1 query per warp, selection reads smem ----
    const int q = warp;
    const uint32_t* row32 = (const uint32_t*)(sc16 + (size_t)q * SS);
    uint32_t* myhist = (uint32_t*)(smem + HIST_OFF) + warp * 256;
    int*      sidx   = (int*)(smem + SIDX_OFF) + warp * 64;
    int*      eidx   = (int*)(smem + EIDX_OFF) + warp * 64;
    float*    svalf  = (float*)(smem + SVAL_OFF) + warp * 64;

    // pass 1: histogram of top byte
    for (int b = lane; b < 256; b += 32) myhist[b] = 0;
    __syncwarp();
#pragma unroll 4
    for (int j = 0; j < 32; j++) {
        uint32_t w2 = row32[j * 32 + lane];
        atomicAdd(&myhist[(w2 >> 8) & 255u], 1u);
        atomicAdd(&myhist[w2 >> 24], 1u);
    }
    __syncwarp();
    int b1d, r1;
    hist_scan(myhist, lane, TOPK, b1d, r1);
    __syncwarp();

    // pass 2: histogram of low byte within bucket b1d
    for (int b = lane; b < 256; b += 32) myhist[b] = 0;
    __syncwarp();
#pragma unroll 4
    for (int j = 0; j < 32; j++) {
        uint32_t w2 = row32[j * 32 + lane];
        if ((int)((w2 >> 8) & 255u) == b1d) atomicAdd(&myhist[w2 & 255u], 1u);
        if ((int)(w2 >> 24) == b1d)         atomicAdd(&myhist[(w2 >> 16) & 255u], 1u);
    }
    __syncwarp();
    int b0sel, r2;
    hist_scan(myhist, lane, r1, b0sel, r2);
    const unsigned T16 = ((unsigned)b1d << 8) | (unsigned)b0sel;

    // pass 3: collect keys > T16, then first r2 == T16 in index order
    {
        int cnt = 0, ecnt = 0;
        unsigned lt = (1u << lane) - 1u;
#pragma unroll 4
        for (int j = 0; j < 32; j++) {
            uint32_t w2 = row32[j * 32 + lane];
            unsigned klo = w2 & 0xFFFFu, khi2 = w2 >> 16;
            int ilo = j * 64 + 2 * lane;
            bool gt = (klo > T16), eq = (klo == T16);
            unsigned mg = __ballot_sync(FULL, gt);
            unsigned me = __ballot_sync(FULL, eq);
            if (gt) sidx[cnt + __popc(mg & lt)] = ilo;
            if (eq) { int p = ecnt + __popc(me & lt); if (p < TOPK) eidx[p] = ilo; }
            cnt += __popc(mg); ecnt += __popc(me);
            gt = (khi2 > T16); eq = (khi2 == T16);
            mg = __ballot_sync(FULL, gt);
            me = __ballot_sync(FULL, eq);
            if (gt) sidx[cnt + __popc(mg & lt)] = ilo + 1;
            if (eq) { int p = ecnt + __popc(me & lt); if (p < TOPK) eidx[p] = ilo + 1; }
            cnt += __popc(mg); ecnt += __popc(me);
        }
        __syncwarp();
        for (int j = lane; j < r2; j += 32) sidx[cnt + j] = eidx[j];
        __syncwarp();
    }

    // ---- load selected keys into registers (used by rescore, softmax, V) ----
    const int k0 = sidx[lane], k1 = sidx[lane + 32];
    const int hsel = lane >> 4;          // 0 = lanes 0-15, 1 = lanes 16-31
    const int dbase4 = 4 * (lane & 15);  // 4 dims per lane

    // ---- exact fp32 rescore: half-warp per key, unroll 4 (8 keys in flight) ----
    {
        float4 qv4 = *(const float4*)(Qb + (size_t)(q0 + q) * DD + dbase4);
#pragma unroll
        for (int p = 0; p < 32; p += 4) {
            const int base = 2 * p + hsel;           // slot of first key
            const int kk = (p < 16) ? k0 : k1;       // compile-time select
            int ka = __shfl_sync(FULL, kk, (base    ) & 31);
            int kb = __shfl_sync(FULL, kk, (base + 2) & 31);
            int kc = __shfl_sync(FULL, kk, (base + 4) & 31);
            int kd = __shfl_sync(FULL, kk, (base + 6) & 31);
            float4 va = *(const float4*)(Kb + (size_t)ka * DD + dbase4);
            float4 vb = *(const float4*)(Kb + (size_t)kb * DD + dbase4);
            float4 vc = *(const float4*)(Kb + (size_t)kc * DD + dbase4);
            float4 vd = *(const float4*)(Kb + (size_t)kd * DD + dbase4);
            float d0 = qv4.x * va.x + qv4.y * va.y + qv4.z * va.z + qv4.w * va.w;
            float d1 = qv4.x * vb.x + qv4.y * vb.y + qv4.z * vb.z + qv4.w * vb.w;
            float d2 = qv4.x * vc.x + qv4.y * vc.y + qv4.z * vc.z + qv4.w * vc.w;
            float d3 = qv4.x * vd.x + qv4.y * vd.y + qv4.z * vd.z + qv4.w * vd.w;
#pragma unroll
            for (int o = 8; o; o >>= 1) {
                d0 += __shfl_xor_sync(FULL, d0, o);
                d1 += __shfl_xor_sync(FULL, d1, o);
                d2 += __shfl_xor_sync(FULL, d2, o);
                d3 += __shfl_xor_sync(FULL, d3, o);
            }
            if ((lane & 15) == 0) {
                svalf[base]     = d0;
                svalf[base + 2] = d1;
                svalf[base + 4] = d2;
                svalf[base + 6] = d3;
            }
        }
        __syncwarp();
    }

    // ---- softmax (exact fp32) + V gather (half-warp per key, LDG.128) ----
    {
        float v0 = svalf[lane], v1 = svalf[lane + 32];
        float m = fmaxf(v0, v1);
#pragma unroll
        for (int o = 16; o; o >>= 1) m = fmaxf(m, __shfl_xor_sync(FULL, m, o));
        float e0 = __expf(v0 - m), e1 = __expf(v1 - m);
        float s = e0 + e1;
#pragma unroll
        for (int o = 16; o; o >>= 1) s += __shfl_xor_sync(FULL, s, o);
        float inv = 1.f / s;
        float w0 = e0 * inv, w1 = e1 * inv;

        float a0 = 0.f, a1 = 0.f, a2 = 0.f, a3 = 0.f;
        // slots 0..31 (weights w0/keys k0): half-warp h handles slot 2i+h
#pragma unroll 8
        for (int i = 0; i < 16; i++) {
            int src = 2 * i + hsel;
            float w = __shfl_sync(FULL, w0, src);
            int key = __shfl_sync(FULL, k0, src);
            float4 vv = *(const float4*)(Vb + (size_t)key * DD + dbase4);
            a0 += w * vv.x; a1 += w * vv.y; a2 += w * vv.z; a3 += w * vv.w;
        }
        // slots 32..63 (weights w1/keys k1)
#pragma unroll 8
        for (int i = 0; i < 16; i++) {
            int src = 2 * i + hsel;
            float w = __shfl_sync(FULL, w1, src);
            int key = __shfl_sync(FULL, k1, src);
            float4 vv = *(const float4*)(Vb + (size_t)key * DD + dbase4);
            a0 += w * vv.x; a1 += w * vv.y; a2 += w * vv.z; a3 += w * vv.w;
        }
        // combine the two half-warps (same dims, disjoint key subsets)
        a0 += __shfl_xor_sync(FULL, a0, 16);
        a1 += __shfl_xor_sync(FULL, a1, 16);
        a2 += __shfl_xor_sync(FULL, a2, 16);
        a3 += __shfl_xor_sync(FULL, a3, 16);
        if (lane < 16) {
            size_t ob = ((size_t)bh * LL + q0 + q) * DD;
            *(float4*)(Og + ob + dbase4) = make_float4(a0, a1, a2, a3);
        }
    }
}

extern "C" void kernel_launch(void* const* d_in, const int* in_sizes, int n_in,
                              void* d_out, int out_size)
{
    (void)in_sizes; (void)n_in; (void)out_size;
    const float* Q = (const float*)d_in[0];
    const float* K = (const float*)d_in[1];
    const float* V = (const float*)d_in[2];
    float* O = (float*)d_out;

    prep_k_kernel<<<PREP_N / 256, 256>>>((const float4*)K);

    cudaFuncSetAttribute(topk_attn_kernel,
                         cudaFuncAttributeMaxDynamicSharedMemorySize, SMEM_BYTES);
    dim3 grid(BB * HH * (LL / QT));   // 4096 CTAs
    topk_attn_kernel<<<grid, NTHREADS, SMEM_BYTES>>>(Q, K, V, O);
}